// round 1
// baseline (speedup 1.0000x reference)
#include <cuda_runtime.h>
#include <cuda_bf16.h>
#include <math.h>

// Problem constants
#define D 512          // feature dim == 2*HID, K for every GEMM
#define HID 256        // N for every layer GEMM
#define B 512
#define S1 25
#define S2 10
#define NCLS 50
#define M1 (B * S2)    // 5120

// ---------------- scratch (device globals; no allocation) ----------------
__device__ float g_agg2[M1 * D];    // mean of h2 groups        [5120,512]
__device__ float g_agg1[B * D];     // mean of h1 groups        [512,512]
__device__ float g_n1[M1 * D];      // layer0 output, hop1      [5120,512]
__device__ float g_n0[B * D];       // layer0 output, hop0      [512,512]
__device__ float g_aggn1[B * D];    // mean of n1 groups        [512,512]
__device__ float g_out[B * D];      // layer1 output            [512,512]

// ---------------- mean over S consecutive (possibly gathered) rows -------
// grid = n_groups, block = 128 threads (each thread owns one float4 column)
__global__ void mean_rows_kernel(const float* __restrict__ feat,
                                 const int* __restrict__ samples, // nullable
                                 const float* __restrict__ dense, // used if samples==0
                                 int S, float inv_s,
                                 float* __restrict__ out)
{
    int g = blockIdx.x;
    int c = threadIdx.x;            // 0..127 -> float4 col
    float4 acc = make_float4(0.f, 0.f, 0.f, 0.f);
    for (int s = 0; s < S; ++s) {
        const float* row;
        if (samples) {
            long r = samples[g * S + s];
            row = feat + r * (long)D;
        } else {
            row = dense + (long)(g * S + s) * D;
        }
        float4 v = __ldg((const float4*)(row) + c);
        acc.x += v.x; acc.y += v.y; acc.z += v.z; acc.w += v.w;
    }
    acc.x *= inv_s; acc.y *= inv_s; acc.z *= inv_s; acc.w *= inv_s;
    ((float4*)(out + (long)g * D))[c] = acc;
}

// ---------------- tiled SGEMM: C[m, colOff+n] = act(A[row(m),:] @ W[:,n]) -
// A: K=512 row-major; optional row gather through idx.
// W: [512, 256] row-major. Output tile 64x64, 256 threads, TM=TN=4, BK=32.
#define BM 64
#define BN 64
#define BK 32
__global__ __launch_bounds__(256, 2)
void gemm512x256_kernel(const float* __restrict__ A,
                        const int* __restrict__ idx,   // nullable
                        const float* __restrict__ W,
                        float* __restrict__ C, int ldc, int colOff,
                        int M, int doRelu)
{
    __shared__ float As[BK][BM];     // A tile, transposed
    __shared__ float Ws[BK][BN];

    const int tid = threadIdx.x;
    const int bm = blockIdx.y * BM;
    const int bn = blockIdx.x * BN;

    const int tr = (tid >> 4) << 2;       // 0..60 step 4
    const int tc = (tid & 15) << 2;       // 0..60 step 4

    // A-load mapping: 64x32 tile = 512 float4; 2 per thread
    const int a_row  = tid >> 3;          // 0..31  (+32 second)
    const int a_col4 = tid & 7;           // float4 within 32-col strip
    // W-load mapping: 32x64 tile = 512 float4; 2 per thread
    const int w_row  = tid >> 4;          // 0..15  (+16 second)
    const int w_col4 = tid & 15;

    // resolve the two gathered A rows once
    long aoff[2];
#pragma unroll
    for (int i = 0; i < 2; ++i) {
        int gr = bm + a_row + i * 32;
        if (gr >= M) gr = M - 1;          // M is a multiple of 64 here; safety only
        long r = idx ? (long)idx[gr] : (long)gr;
        aoff[i] = r * (long)D;
    }

    float acc[4][4];
#pragma unroll
    for (int i = 0; i < 4; ++i)
#pragma unroll
        for (int j = 0; j < 4; ++j) acc[i][j] = 0.f;

    for (int k0 = 0; k0 < D; k0 += BK) {
#pragma unroll
        for (int i = 0; i < 2; ++i) {
            float4 v = __ldg((const float4*)(A + aoff[i] + k0) + a_col4);
            int r = a_row + i * 32;
            As[a_col4 * 4 + 0][r] = v.x;
            As[a_col4 * 4 + 1][r] = v.y;
            As[a_col4 * 4 + 2][r] = v.z;
            As[a_col4 * 4 + 3][r] = v.w;
        }
#pragma unroll
        for (int i = 0; i < 2; ++i) {
            int r = w_row + i * 16;
            float4 v = __ldg((const float4*)(W + (long)(k0 + r) * HID + bn) + w_col4);
            *(float4*)&Ws[r][w_col4 * 4] = v;
        }
        __syncthreads();
#pragma unroll
        for (int kk = 0; kk < BK; ++kk) {
            float a[4], b[4];
#pragma unroll
            for (int i = 0; i < 4; ++i) a[i] = As[kk][tr + i];
#pragma unroll
            for (int j = 0; j < 4; ++j) b[j] = Ws[kk][tc + j];
#pragma unroll
            for (int i = 0; i < 4; ++i)
#pragma unroll
                for (int j = 0; j < 4; ++j) acc[i][j] = fmaf(a[i], b[j], acc[i][j]);
        }
        __syncthreads();
    }

#pragma unroll
    for (int i = 0; i < 4; ++i) {
        int r = bm + tr + i;
        if (r < M) {
            float4 v;
            v.x = acc[i][0]; v.y = acc[i][1]; v.z = acc[i][2]; v.w = acc[i][3];
            if (doRelu) {
                v.x = fmaxf(v.x, 0.f); v.y = fmaxf(v.y, 0.f);
                v.z = fmaxf(v.z, 0.f); v.w = fmaxf(v.w, 0.f);
            }
            *(float4*)(C + (long)r * ldc + colOff + bn + tc) = v;
        }
    }
}

// ---------------- normalize rows of out[512,512], then logits ------------
// grid = B rows, 128 threads
__global__ void finalize_kernel(const float* __restrict__ outb,
                                const float* __restrict__ Wp,   // [512,50]
                                const float* __restrict__ bp,   // [50]
                                float* __restrict__ logits)     // [512,50]
{
    int b = blockIdx.x;
    int t = threadIdx.x;
    __shared__ float row[D];
    __shared__ float wss[4];

    float ss = 0.f;
#pragma unroll
    for (int i = 0; i < 4; ++i) {
        int k = t + i * 128;
        float v = outb[(long)b * D + k];
        row[k] = v;
        ss += v * v;
    }
#pragma unroll
    for (int o = 16; o; o >>= 1) ss += __shfl_xor_sync(0xffffffffu, ss, o);
    if ((t & 31) == 0) wss[t >> 5] = ss;
    __syncthreads();
    float inv = 1.f / fmaxf(sqrtf(wss[0] + wss[1] + wss[2] + wss[3]), 1e-12f);

    if (t < NCLS) {
        float acc = 0.f;
#pragma unroll 4
        for (int k = 0; k < D; ++k) acc = fmaf(row[k], Wp[k * NCLS + t], acc);
        logits[(long)b * NCLS + t] = acc * inv + bp[t];
    }
}

// --------------------------------------------------------------------------
extern "C" void kernel_launch(void* const* d_in, const int* in_sizes, int n_in,
                              void* d_out, int out_size)
{
    const float* features = (const float*)d_in[0];
    const float* W_self0  = (const float*)d_in[1];
    const float* W_neigh0 = (const float*)d_in[2];
    const float* W_self1  = (const float*)d_in[3];
    const float* W_neigh1 = (const float*)d_in[4];
    const float* W_pred   = (const float*)d_in[5];
    const float* b_pred   = (const float*)d_in[6];
    const int*   samples0 = (const int*)d_in[7];
    const int*   samples1 = (const int*)d_in[8];
    const int*   samples2 = (const int*)d_in[9];
    float* logits = (float*)d_out;

    float *agg2, *agg1, *n1, *n0, *aggn1, *outb;
    cudaGetSymbolAddress((void**)&agg2,  g_agg2);
    cudaGetSymbolAddress((void**)&agg1,  g_agg1);
    cudaGetSymbolAddress((void**)&n1,    g_n1);
    cudaGetSymbolAddress((void**)&n0,    g_n0);
    cudaGetSymbolAddress((void**)&aggn1, g_aggn1);
    cudaGetSymbolAddress((void**)&outb,  g_out);

    // 1) neighbor means of raw features
    mean_rows_kernel<<<M1, 128>>>(features, samples2, nullptr, S1, 1.f / S1, agg2);
    mean_rows_kernel<<<B, 128>>>(features, samples1, nullptr, S2, 1.f / S2, agg1);

    // 2) layer 0 (relu): n1 = [h1@Ws0 | agg2@Wn0], n0 = [h0@Ws0 | agg1@Wn0]
    {
        dim3 grid(HID / BN, M1 / BM);
        gemm512x256_kernel<<<grid, 256>>>(features, samples1, W_self0,  n1, D, 0,   M1, 1);
        gemm512x256_kernel<<<grid, 256>>>(agg2,     nullptr,  W_neigh0, n1, D, HID, M1, 1);
    }
    {
        dim3 grid(HID / BN, B / BM);
        gemm512x256_kernel<<<grid, 256>>>(features, samples0, W_self0,  n0, D, 0,   B, 1);
        gemm512x256_kernel<<<grid, 256>>>(agg1,     nullptr,  W_neigh0, n0, D, HID, B, 1);
    }

    // 3) mean of n1 groups
    mean_rows_kernel<<<B, 128>>>(nullptr, nullptr, n1, S2, 1.f / S2, aggn1);

    // 4) layer 1 (identity): out = [n0@Ws1 | aggn1@Wn1]
    {
        dim3 grid(HID / BN, B / BM);
        gemm512x256_kernel<<<grid, 256>>>(n0,    nullptr, W_self1,  outb, D, 0,   B, 0);
        gemm512x256_kernel<<<grid, 256>>>(aggn1, nullptr, W_neigh1, outb, D, HID, B, 0);
    }

    // 5) row-normalize + logits
    finalize_kernel<<<B, 128>>>(outb, W_pred, b_pred, logits);
}

// round 2
// speedup vs baseline: 1.5690x; 1.5690x over previous
#include <cuda_runtime.h>
#include <cuda_bf16.h>
#include <math.h>

// Problem constants
#define D 512          // feature dim == 2*HID, K for every GEMM
#define HID 256        // N for every layer GEMM
#define B 512
#define S1 25
#define S2 10
#define NCLS 50
#define M1 (B * S2)    // 5120

// ---------------- scratch (device globals; no allocation) ----------------
__device__ float g_agg2[M1 * D];    // mean of h2 groups        [5120,512]
__device__ float g_agg1[B * D];     // mean of h1 groups        [512,512]
__device__ float g_n1[M1 * D];      // layer0 output, hop1      [5120,512]
__device__ float g_n0[B * D];       // layer0 output, hop0      [512,512]
__device__ float g_aggn1[B * D];    // mean of n1 groups        [512,512]
__device__ float g_out[B * D];      // layer1 output            [512,512]

// ---------------- mean over S consecutive (possibly gathered) rows -------
// grid = n_groups, block = 128 threads (each thread owns one float4 column)
template<int S>
__global__ void mean_rows_kernel(const float* __restrict__ src,
                                 const int* __restrict__ samples, // nullable
                                 float* __restrict__ out)
{
    const int g = blockIdx.x;
    const int c = threadIdx.x;            // 0..127 -> float4 col
    float4 a0 = make_float4(0.f, 0.f, 0.f, 0.f);
    float4 a1 = make_float4(0.f, 0.f, 0.f, 0.f);
#pragma unroll
    for (int s = 0; s < S; ++s) {
        long r = samples ? (long)samples[g * S + s] : (long)(g * S + s);
        float4 v = __ldg((const float4*)(src + r * (long)D) + c);
        if (s & 1) { a1.x += v.x; a1.y += v.y; a1.z += v.z; a1.w += v.w; }
        else       { a0.x += v.x; a0.y += v.y; a0.z += v.z; a0.w += v.w; }
    }
    const float inv = 1.f / (float)S;
    float4 o;
    o.x = (a0.x + a1.x) * inv;  o.y = (a0.y + a1.y) * inv;
    o.z = (a0.z + a1.z) * inv;  o.w = (a0.w + a1.w) * inv;
    ((float4*)(out + (long)g * D))[c] = o;
}

// ---------------- dual tiled SGEMM -----------------------------------------
// z = blockIdx.z selects (A0,idx0,W0)->C[:,0:256] or (A1,idx1,W1)->C[:,256:512]
// A: [M(gathered), 512] fp32 row-major; W: [512, 256] fp32 row-major.
// Tile BM x BN, BK=16, 256 threads, microtile TM x TN, double-buffered smem.
template<int BM, int BN, int TM, int TN>
__global__ __launch_bounds__(256, 2)
void gemm_dual_kernel(const float* __restrict__ A0, const int* __restrict__ idx0,
                      const float* __restrict__ W0,
                      const float* __restrict__ A1, const int* __restrict__ idx1,
                      const float* __restrict__ W1,
                      float* __restrict__ C, int M, int doRelu)
{
    constexpr int BK  = 16;
    constexpr int TX  = BN / TN;            // threads per row of thread-grid
    constexpr int NA  = (BM * 4) / 256;     // A float4 loads per thread
    constexpr int LDA = BM + 4;             // padded to break STS conflicts

    __shared__ __align__(16) float As[2][BK][LDA];
    __shared__ __align__(16) float Ws[2][BK][BN];

    const float* __restrict__ A  = blockIdx.z ? A1  : A0;
    const int*   __restrict__ idx= blockIdx.z ? idx1: idx0;
    const float* __restrict__ W  = blockIdx.z ? W1  : W0;
    const int colOff = blockIdx.z * HID;

    const int tid = threadIdx.x;
    const int bm  = blockIdx.y * BM;
    const int bn  = blockIdx.x * BN;
    const int tr  = (tid / TX) * TM;
    const int tc  = (tid % TX) * TN;

    // ---- A load mapping: float4 index i = tid + j*256; row = i>>2, col4 = i&3
    const int acol = (tid & 3) << 2;        // element col within k-tile (0,4,8,12)
    int  arow[NA];
    long aoff[NA];
#pragma unroll
    for (int j = 0; j < NA; ++j) {
        arow[j] = (tid >> 2) + j * 64;
        int gr = bm + arow[j];
        long r = idx ? (long)__ldg(idx + gr) : (long)gr;
        aoff[j] = r * (long)D + acol;
    }
    // ---- W load mapping: 256 float4 = 16 rows x 16 float4/row, 1 per thread
    const int wrow = tid >> 4;              // 0..15
    const int wcol = (tid & 15) << 2;       // 0..60

    float acc[TM][TN];
#pragma unroll
    for (int i = 0; i < TM; ++i)
#pragma unroll
        for (int j = 0; j < TN; ++j) acc[i][j] = 0.f;

    float4 pa[NA];
    float4 pw;

    // prefetch k-tile 0
#pragma unroll
    for (int j = 0; j < NA; ++j) pa[j] = __ldg((const float4*)(A + aoff[j]));
    pw = __ldg((const float4*)(W + (long)wrow * HID + bn + wcol));

    // store to buffer 0
#pragma unroll
    for (int j = 0; j < NA; ++j) {
        As[0][acol + 0][arow[j]] = pa[j].x;
        As[0][acol + 1][arow[j]] = pa[j].y;
        As[0][acol + 2][arow[j]] = pa[j].z;
        As[0][acol + 3][arow[j]] = pa[j].w;
    }
    *(float4*)&Ws[0][wrow][wcol] = pw;
    __syncthreads();

    constexpr int NKT = D / BK;             // 32
#pragma unroll 1
    for (int kt = 0; kt < NKT; ++kt) {
        const int cur = kt & 1;
        if (kt + 1 < NKT) {
            const int k0 = (kt + 1) * BK;
#pragma unroll
            for (int j = 0; j < NA; ++j)
                pa[j] = __ldg((const float4*)(A + aoff[j] + k0));
            pw = __ldg((const float4*)(W + (long)(k0 + wrow) * HID + bn + wcol));
        }
#pragma unroll
        for (int kk = 0; kk < BK; ++kk) {
            float a[TM], b[TN];
#pragma unroll
            for (int i = 0; i < TM; i += 4)
                *(float4*)&a[i] = *(const float4*)&As[cur][kk][tr + i];
#pragma unroll
            for (int j = 0; j < TN; j += 4)
                *(float4*)&b[j] = *(const float4*)&Ws[cur][kk][tc + j];
#pragma unroll
            for (int i = 0; i < TM; ++i)
#pragma unroll
                for (int j = 0; j < TN; ++j)
                    acc[i][j] = fmaf(a[i], b[j], acc[i][j]);
        }
        if (kt + 1 < NKT) {
            const int nxt = cur ^ 1;
#pragma unroll
            for (int j = 0; j < NA; ++j) {
                As[nxt][acol + 0][arow[j]] = pa[j].x;
                As[nxt][acol + 1][arow[j]] = pa[j].y;
                As[nxt][acol + 2][arow[j]] = pa[j].z;
                As[nxt][acol + 3][arow[j]] = pa[j].w;
            }
            *(float4*)&Ws[nxt][wrow][wcol] = pw;
            __syncthreads();
        }
    }

    // epilogue
#pragma unroll
    for (int i = 0; i < TM; ++i) {
        const int r = bm + tr + i;
#pragma unroll
        for (int j = 0; j < TN; j += 4) {
            float4 v;
            v.x = acc[i][j + 0]; v.y = acc[i][j + 1];
            v.z = acc[i][j + 2]; v.w = acc[i][j + 3];
            if (doRelu) {
                v.x = fmaxf(v.x, 0.f); v.y = fmaxf(v.y, 0.f);
                v.z = fmaxf(v.z, 0.f); v.w = fmaxf(v.w, 0.f);
            }
            *(float4*)(C + (long)r * D + colOff + bn + tc + j) = v;
        }
    }
}

// ---------------- normalize rows of out[512,512], then logits ------------
// grid = B rows, 128 threads
__global__ void finalize_kernel(const float* __restrict__ outb,
                                const float* __restrict__ Wp,   // [512,50]
                                const float* __restrict__ bp,   // [50]
                                float* __restrict__ logits)     // [512,50]
{
    int b = blockIdx.x;
    int t = threadIdx.x;
    __shared__ float row[D];
    __shared__ float wss[4];

    float ss = 0.f;
#pragma unroll
    for (int i = 0; i < 4; ++i) {
        int k = t + i * 128;
        float v = outb[(long)b * D + k];
        row[k] = v;
        ss += v * v;
    }
#pragma unroll
    for (int o = 16; o; o >>= 1) ss += __shfl_xor_sync(0xffffffffu, ss, o);
    if ((t & 31) == 0) wss[t >> 5] = ss;
    __syncthreads();
    float inv = 1.f / fmaxf(sqrtf(wss[0] + wss[1] + wss[2] + wss[3]), 1e-12f);

    if (t < NCLS) {
        float acc = 0.f;
#pragma unroll 8
        for (int k = 0; k < D; ++k) acc = fmaf(row[k], Wp[k * NCLS + t], acc);
        logits[(long)b * NCLS + t] = acc * inv + bp[t];
    }
}

// --------------------------------------------------------------------------
extern "C" void kernel_launch(void* const* d_in, const int* in_sizes, int n_in,
                              void* d_out, int out_size)
{
    const float* features = (const float*)d_in[0];
    const float* W_self0  = (const float*)d_in[1];
    const float* W_neigh0 = (const float*)d_in[2];
    const float* W_self1  = (const float*)d_in[3];
    const float* W_neigh1 = (const float*)d_in[4];
    const float* W_pred   = (const float*)d_in[5];
    const float* b_pred   = (const float*)d_in[6];
    const int*   samples0 = (const int*)d_in[7];
    const int*   samples1 = (const int*)d_in[8];
    const int*   samples2 = (const int*)d_in[9];
    float* logits = (float*)d_out;

    float *agg2, *agg1, *n1, *n0, *aggn1, *outb;
    cudaGetSymbolAddress((void**)&agg2,  g_agg2);
    cudaGetSymbolAddress((void**)&agg1,  g_agg1);
    cudaGetSymbolAddress((void**)&n1,    g_n1);
    cudaGetSymbolAddress((void**)&n0,    g_n0);
    cudaGetSymbolAddress((void**)&aggn1, g_aggn1);
    cudaGetSymbolAddress((void**)&outb,  g_out);

    // 1) neighbor means of raw features (DRAM-bound gathers)
    mean_rows_kernel<S1><<<M1, 128>>>(features, samples2, agg2);
    mean_rows_kernel<S2><<<B,  128>>>(features, samples1, agg1);

    // 2) layer 0 (relu), both halves in one launch via grid.z:
    //    n1[:,0:256] = relu(h1 @ Ws0), n1[:,256:512] = relu(agg2 @ Wn0)
    {
        dim3 grid(HID / 64, M1 / 128, 2);
        gemm_dual_kernel<128, 64, 8, 4><<<grid, 256>>>(
            features, samples1, W_self0,
            agg2,     nullptr,  W_neigh0,
            n1, M1, 1);
    }
    //    n0[:,0:256] = relu(h0 @ Ws0), n0[:,256:512] = relu(agg1 @ Wn0)
    {
        dim3 grid(HID / 64, B / 64, 2);
        gemm_dual_kernel<64, 64, 4, 4><<<grid, 256>>>(
            features, samples0, W_self0,
            agg1,     nullptr,  W_neigh0,
            n0, B, 1);
    }

    // 3) mean of n1 groups
    mean_rows_kernel<S2><<<B, 128>>>(n1, nullptr, aggn1);

    // 4) layer 1 (identity): out = [n0@Ws1 | aggn1@Wn1]
    {
        dim3 grid(HID / 64, B / 64, 2);
        gemm_dual_kernel<64, 64, 4, 4><<<grid, 256>>>(
            n0,    nullptr, W_self1,
            aggn1, nullptr, W_neigh1,
            outb, B, 0);
    }

    // 5) row-normalize + logits
    finalize_kernel<<<B, 128>>>(outb, W_pred, b_pred, logits);
}

// round 4
// speedup vs baseline: 1.9331x; 1.2321x over previous
#include <cuda_runtime.h>
#include <cuda_bf16.h>
#include <math.h>
#include <stdint.h>

// Problem constants
#define D 512          // feature dim == 2*HID, K for every GEMM
#define HID 256        // N for every layer GEMM
#define B 512
#define S1 25
#define S2 10
#define NCLS 50
#define M1 (B * S2)    // 5120

// ---------------- scratch (device globals; no allocation) ----------------
__device__ float g_agg2[M1 * D];
__device__ float g_agg1[B * D];
__device__ float g_n1[M1 * D];
__device__ float g_n0[B * D];
__device__ float g_aggn1[B * D];
__device__ float g_out[B * D];
// pre-converted weights: 4 matrices, each W^T as [HID rows(N), D cols(K)] bf16
__device__ __nv_bfloat16 g_wt_hi[4 * HID * D];
__device__ __nv_bfloat16 g_wt_lo[4 * HID * D];

// split fp32 -> (hi, lo) bf16; pack two values into one u32
__device__ __forceinline__ void cvt2(float x, float y, uint32_t& hp, uint32_t& lp) {
    __nv_bfloat16 hx = __float2bfloat16_rn(x);
    __nv_bfloat16 hy = __float2bfloat16_rn(y);
    __nv_bfloat16 lx = __float2bfloat16_rn(x - __bfloat162float(hx));
    __nv_bfloat16 ly = __float2bfloat16_rn(y - __bfloat162float(hy));
    hp = (uint32_t)__bfloat16_as_ushort(hx) | ((uint32_t)__bfloat16_as_ushort(hy) << 16);
    lp = (uint32_t)__bfloat16_as_ushort(lx) | ((uint32_t)__bfloat16_as_ushort(ly) << 16);
}

#define MMA_BF16(d, a, b) \
    asm volatile( \
        "mma.sync.aligned.m16n8k16.row.col.f32.bf16.bf16.f32 " \
        "{%0,%1,%2,%3}, {%4,%5,%6,%7}, {%8,%9}, {%0,%1,%2,%3};" \
        : "+f"((d)[0]), "+f"((d)[1]), "+f"((d)[2]), "+f"((d)[3]) \
        : "r"((a)[0]), "r"((a)[1]), "r"((a)[2]), "r"((a)[3]), \
          "r"((b)[0]), "r"((b)[1]))

// ---------------- mean over S consecutive (possibly gathered) rows -------
template<int S>
__global__ void mean_rows_kernel(const float* __restrict__ src,
                                 const int* __restrict__ samples,
                                 float* __restrict__ out)
{
    const int g = blockIdx.x;
    const int c = threadIdx.x;
    float4 a0 = make_float4(0.f, 0.f, 0.f, 0.f);
    float4 a1 = make_float4(0.f, 0.f, 0.f, 0.f);
#pragma unroll
    for (int s = 0; s < S; ++s) {
        long r = samples ? (long)samples[g * S + s] : (long)(g * S + s);
        float4 v = __ldg((const float4*)(src + r * (long)D) + c);
        if (s & 1) { a1.x += v.x; a1.y += v.y; a1.z += v.z; a1.w += v.w; }
        else       { a0.x += v.x; a0.y += v.y; a0.z += v.z; a0.w += v.w; }
    }
    const float inv = 1.f / (float)S;
    float4 o;
    o.x = (a0.x + a1.x) * inv;  o.y = (a0.y + a1.y) * inv;
    o.z = (a0.z + a1.z) * inv;  o.w = (a0.w + a1.w) * inv;
    ((float4*)(out + (long)g * D))[c] = o;
}

// ---------------- weight convert+transpose: W[512,256] -> Wt hi/lo [256,512]
__global__ void convert_w_kernel(const float* __restrict__ W0, const float* __restrict__ W1,
                                 const float* __restrict__ W2, const float* __restrict__ W3,
                                 __nv_bfloat16* __restrict__ hi, __nv_bfloat16* __restrict__ lo)
{
    const float* W = (blockIdx.z == 0) ? W0 : (blockIdx.z == 1) ? W1 : (blockIdx.z == 2) ? W2 : W3;
    __nv_bfloat16* h = hi + (long)blockIdx.z * HID * D;
    __nv_bfloat16* l = lo + (long)blockIdx.z * HID * D;
    int t = blockIdx.x * 256 + threadIdx.x;      // 0..131071
    int n = t & (HID - 1);
    int k = t >> 8;
    float v = __ldg(W + (long)k * HID + n);
    __nv_bfloat16 hb = __float2bfloat16_rn(v);
    __nv_bfloat16 lb = __float2bfloat16_rn(v - __bfloat162float(hb));
    h[(long)n * D + k] = hb;
    l[(long)n * D + k] = lb;
}

// ---------------- split-bf16 mma.sync GEMM ---------------------------------
// C[BM rows at bm, 64 cols at colOff] = act(A[row(m),:512] @ Wt^T), Wt [N,K] bf16 hi/lo.
// blockIdx.z selects (A0,idx0,B0)->cols[0:256] or (A1,idx1,B1)->cols[256:512].
// 256 threads = 8 warps. BM=128: warp grid 4x2 (warp tile 32x32).
//                         BM=64 : warp grid 2x4 (warp tile 32x16).
template<int BM, int RELU>
__global__ void __launch_bounds__(256, 2)
gemm_mma_kernel(const float* __restrict__ A0, const int* __restrict__ idx0,
                const __nv_bfloat16* __restrict__ B0h, const __nv_bfloat16* __restrict__ B0l,
                const float* __restrict__ A1, const int* __restrict__ idx1,
                const __nv_bfloat16* __restrict__ B1h, const __nv_bfloat16* __restrict__ B1l,
                float* __restrict__ C)
{
    constexpr int BN  = 64;
    constexpr int KC  = 32;                 // k per chunk
    constexpr int SLD = 40;                 // smem row stride (bf16 elems), pad for banks
    constexpr int WM  = BM / 32;            // warps along M
    constexpr int WN  = 8 / WM;             // warps along N
    constexpr int NSP = BN / WN;            // warp n-span
    constexpr int NT  = NSP / 8;            // 8-col n-tiles per warp
    constexpr int ABUF = BM * SLD;          // bf16 elems
    constexpr int BBUF = BN * SLD;
    constexpr int BUF  = 2 * ABUF + 2 * BBUF;
    constexpr int NAL  = BM * 8 / 256;      // A float4 loads per thread

    extern __shared__ __align__(16) uint16_t sm[];

    const float* A; const int* idx; const __nv_bfloat16 *Bh, *Bl;
    if (blockIdx.z) { A = A1; idx = idx1; Bh = B1h; Bl = B1l; }
    else            { A = A0; idx = idx0; Bh = B0h; Bl = B0l; }
    const int bm = blockIdx.y * BM;
    const int bn = blockIdx.x * BN;
    const int colOff = blockIdx.z * HID + bn;

    const int tid  = threadIdx.x;
    const int warp = tid >> 5, lane = tid & 31;
    const int g  = lane >> 2, tg = lane & 3;
    const int wm = warp / WN, wn = warp % WN;

    // ---- global load mappings
    const float4* ap[NAL]; int as_u32[NAL];           // A: fp32 gmem -> hi/lo smem
#pragma unroll
    for (int j = 0; j < NAL; ++j) {
        int flat = tid + j * 256;
        int row = flat >> 3, c4 = flat & 7;           // 8 float4 per row per chunk
        long r = idx ? (long)__ldg(idx + bm + row) : (long)(bm + row);
        ap[j] = (const float4*)(A + r * (long)D) + c4;
        as_u32[j] = row * (SLD / 2) + c4 * 2;         // uint32 index
    }
    const uint4* bph; const uint4* bpl; int bs_u4;    // B: bf16 gmem -> smem copy
    {
        int row = tid >> 2, c = tid & 3;              // 4 uint4 per row per chunk
        bph = (const uint4*)(Bh + (long)(bn + row) * D) + c;
        bpl = (const uint4*)(Bl + (long)(bn + row) * D) + c;
        bs_u4 = row * (SLD / 8) + c;                  // uint4 index (SLD*2/16)
    }

    float acc[2][NT][4];
#pragma unroll
    for (int mt = 0; mt < 2; ++mt)
#pragma unroll
        for (int nt = 0; nt < NT; ++nt)
#pragma unroll
            for (int q = 0; q < 4; ++q) acc[mt][nt][q] = 0.f;

    float4 pa[NAL]; uint4 pbh, pbl;

    // prefetch + store chunk 0
#pragma unroll
    for (int j = 0; j < NAL; ++j) pa[j] = __ldg(ap[j]);
    pbh = __ldg(bph); pbl = __ldg(bpl);
    {
        uint32_t* Ah = (uint32_t*)(sm);
        uint32_t* Al = (uint32_t*)(sm + ABUF);
        uint4*    Bh4 = (uint4*)(sm + 2 * ABUF);
        uint4*    Bl4 = (uint4*)(sm + 2 * ABUF + BBUF);
#pragma unroll
        for (int j = 0; j < NAL; ++j) {
            uint32_t h0, l0, h1, l1;
            cvt2(pa[j].x, pa[j].y, h0, l0);
            cvt2(pa[j].z, pa[j].w, h1, l1);
            Ah[as_u32[j]] = h0; Ah[as_u32[j] + 1] = h1;
            Al[as_u32[j]] = l0; Al[as_u32[j] + 1] = l1;
        }
        Bh4[bs_u4] = pbh; Bl4[bs_u4] = pbl;
    }
    __syncthreads();

    constexpr int NKT = D / KC;             // 16 chunks
#pragma unroll 1
    for (int kt = 0; kt < NKT; ++kt) {
        const int cur = kt & 1;
        if (kt + 1 < NKT) {
#pragma unroll
            for (int j = 0; j < NAL; ++j) pa[j] = __ldg(ap[j] + (kt + 1) * 8);
            pbh = __ldg(bph + (kt + 1) * 4);
            pbl = __ldg(bpl + (kt + 1) * 4);
        }
        // ---- compute on buffer cur
        const uint32_t* Ah = (const uint32_t*)(sm + cur * BUF);
        const uint32_t* Al = Ah + ABUF / 2;
        const uint32_t* Bh32 = Ah + ABUF;           // (2*ABUF bf16)/2
        const uint32_t* Bl32 = Bh32 + BBUF / 2;
#pragma unroll
        for (int kk = 0; kk < KC; kk += 16) {
            const int kc = kk / 2;
            uint32_t ah[2][4], al[2][4], bhf[NT][2], blf[NT][2];
#pragma unroll
            for (int mt = 0; mt < 2; ++mt) {
                int m0 = wm * 32 + mt * 16;
                int i0 = (m0 + g) * (SLD / 2) + kc + tg;
                int i1 = (m0 + g + 8) * (SLD / 2) + kc + tg;
                ah[mt][0] = Ah[i0];     ah[mt][1] = Ah[i1];
                ah[mt][2] = Ah[i0 + 4]; ah[mt][3] = Ah[i1 + 4];
                al[mt][0] = Al[i0];     al[mt][1] = Al[i1];
                al[mt][2] = Al[i0 + 4]; al[mt][3] = Al[i1 + 4];
            }
#pragma unroll
            for (int nt = 0; nt < NT; ++nt) {
                int n0 = wn * NSP + nt * 8;
                int i0 = (n0 + g) * (SLD / 2) + kc + tg;
                bhf[nt][0] = Bh32[i0]; bhf[nt][1] = Bh32[i0 + 4];
                blf[nt][0] = Bl32[i0]; blf[nt][1] = Bl32[i0 + 4];
            }
#pragma unroll
            for (int mt = 0; mt < 2; ++mt)
#pragma unroll
                for (int nt = 0; nt < NT; ++nt) MMA_BF16(acc[mt][nt], ah[mt], bhf[nt]);
#pragma unroll
            for (int mt = 0; mt < 2; ++mt)
#pragma unroll
                for (int nt = 0; nt < NT; ++nt) MMA_BF16(acc[mt][nt], ah[mt], blf[nt]);
#pragma unroll
            for (int mt = 0; mt < 2; ++mt)
#pragma unroll
                for (int nt = 0; nt < NT; ++nt) MMA_BF16(acc[mt][nt], al[mt], bhf[nt]);
        }
        if (kt + 1 < NKT) {
            __syncthreads();
            uint32_t* Ahn = (uint32_t*)(sm + (cur ^ 1) * BUF);
            uint32_t* Aln = Ahn + ABUF / 2;
            uint4*    Bh4 = (uint4*)(Ahn + ABUF);
            uint4*    Bl4 = (uint4*)((uint16_t*)Bh4 + BBUF);
#pragma unroll
            for (int j = 0; j < NAL; ++j) {
                uint32_t h0, l0, h1, l1;
                cvt2(pa[j].x, pa[j].y, h0, l0);
                cvt2(pa[j].z, pa[j].w, h1, l1);
                Ahn[as_u32[j]] = h0; Ahn[as_u32[j] + 1] = h1;
                Aln[as_u32[j]] = l0; Aln[as_u32[j] + 1] = l1;
            }
            Bh4[bs_u4] = pbh; Bl4[bs_u4] = pbl;
            __syncthreads();
        }
    }

    // ---- epilogue: each thread owns C[g][tg*2..+1] and C[g+8][tg*2..+1] per tile
#pragma unroll
    for (int mt = 0; mt < 2; ++mt) {
        int r0 = bm + wm * 32 + mt * 16 + g;
#pragma unroll
        for (int nt = 0; nt < NT; ++nt) {
            int col = colOff + wn * NSP + nt * 8 + tg * 2;
            float2 v0, v1;
            v0.x = acc[mt][nt][0]; v0.y = acc[mt][nt][1];
            v1.x = acc[mt][nt][2]; v1.y = acc[mt][nt][3];
            if (RELU) {
                v0.x = fmaxf(v0.x, 0.f); v0.y = fmaxf(v0.y, 0.f);
                v1.x = fmaxf(v1.x, 0.f); v1.y = fmaxf(v1.y, 0.f);
            }
            *(float2*)(C + (long)r0 * D + col)       = v0;
            *(float2*)(C + (long)(r0 + 8) * D + col) = v1;
        }
    }
}

// ---------------- normalize rows of out[512,512], then logits ------------
__global__ void finalize_kernel(const float* __restrict__ outb,
                                const float* __restrict__ Wp,
                                const float* __restrict__ bp,
                                float* __restrict__ logits)
{
    int b = blockIdx.x;
    int t = threadIdx.x;
    __shared__ float row[D];
    __shared__ float wss[4];

    float ss = 0.f;
#pragma unroll
    for (int i = 0; i < 4; ++i) {
        int k = t + i * 128;
        float v = outb[(long)b * D + k];
        row[k] = v;
        ss += v * v;
    }
#pragma unroll
    for (int o = 16; o; o >>= 1) ss += __shfl_xor_sync(0xffffffffu, ss, o);
    if ((t & 31) == 0) wss[t >> 5] = ss;
    __syncthreads();
    float inv = 1.f / fmaxf(sqrtf(wss[0] + wss[1] + wss[2] + wss[3]), 1e-12f);

    if (t < NCLS) {
        float acc = 0.f;
#pragma unroll 8
        for (int k = 0; k < D; ++k) acc = fmaf(row[k], Wp[k * NCLS + t], acc);
        logits[(long)b * NCLS + t] = acc * inv + bp[t];
    }
}

// --------------------------------------------------------------------------
extern "C" void kernel_launch(void* const* d_in, const int* in_sizes, int n_in,
                              void* d_out, int out_size)
{
    const float* features = (const float*)d_in[0];
    const float* W_self0  = (const float*)d_in[1];
    const float* W_neigh0 = (const float*)d_in[2];
    const float* W_self1  = (const float*)d_in[3];
    const float* W_neigh1 = (const float*)d_in[4];
    const float* W_pred   = (const float*)d_in[5];
    const float* b_pred   = (const float*)d_in[6];
    const int*   samples0 = (const int*)d_in[7];
    const int*   samples1 = (const int*)d_in[8];
    const int*   samples2 = (const int*)d_in[9];
    float* logits = (float*)d_out;

    float *agg2, *agg1, *n1, *n0, *aggn1, *outb;
    __nv_bfloat16 *wth, *wtl;
    cudaGetSymbolAddress((void**)&agg2,  g_agg2);
    cudaGetSymbolAddress((void**)&agg1,  g_agg1);
    cudaGetSymbolAddress((void**)&n1,    g_n1);
    cudaGetSymbolAddress((void**)&n0,    g_n0);
    cudaGetSymbolAddress((void**)&aggn1, g_aggn1);
    cudaGetSymbolAddress((void**)&outb,  g_out);
    cudaGetSymbolAddress((void**)&wth,   g_wt_hi);
    cudaGetSymbolAddress((void**)&wtl,   g_wt_lo);

    const int WSZ = HID * D;

    // dynamic smem: 2 buffers * (2*BM*40 + 2*64*40) bf16 elems * 2B
    constexpr int SM128 = 2 * (2 * 128 * 40 + 2 * 64 * 40) * 2;  // 61440
    constexpr int SM64  = 2 * (2 * 64 * 40 + 2 * 64 * 40) * 2;   // 40960
    cudaFuncSetAttribute(gemm_mma_kernel<128, 1>, cudaFuncAttributeMaxDynamicSharedMemorySize, SM128);
    cudaFuncSetAttribute(gemm_mma_kernel<64, 1>,  cudaFuncAttributeMaxDynamicSharedMemorySize, SM64);
    cudaFuncSetAttribute(gemm_mma_kernel<64, 0>,  cudaFuncAttributeMaxDynamicSharedMemorySize, SM64);

    // 0) convert + transpose all weight matrices to bf16 hi/lo
    convert_w_kernel<<<dim3(512, 1, 4), 256>>>(W_self0, W_neigh0, W_self1, W_neigh1, wth, wtl);

    // 1) neighbor means of raw features
    mean_rows_kernel<S1><<<M1, 128>>>(features, samples2, agg2);
    mean_rows_kernel<S2><<<B,  128>>>(features, samples1, agg1);

    // 2) layer 0 (relu): n1 = [h1@Ws0 | agg2@Wn0]   (M=5120)
    gemm_mma_kernel<128, 1><<<dim3(HID / 64, M1 / 128, 2), 256, SM128>>>(
        features, samples1, wth + 0 * WSZ, wtl + 0 * WSZ,
        agg2,     nullptr,  wth + 1 * WSZ, wtl + 1 * WSZ, n1);

    //    n0 = [h0@Ws0 | agg1@Wn0]   (M=512)
    gemm_mma_kernel<64, 1><<<dim3(HID / 64, B / 64, 2), 256, SM64>>>(
        features, samples0, wth + 0 * WSZ, wtl + 0 * WSZ,
        agg1,     nullptr,  wth + 1 * WSZ, wtl + 1 * WSZ, n0);

    // 3) mean of n1 groups
    mean_rows_kernel<S2><<<B, 128>>>(n1, nullptr, aggn1);

    // 4) layer 1 (identity): out = [n0@Ws1 | aggn1@Wn1]
    gemm_mma_kernel<64, 0><<<dim3(HID / 64, B / 64, 2), 256, SM64>>>(
        n0,    nullptr, wth + 2 * WSZ, wtl + 2 * WSZ,
        aggn1, nullptr, wth + 3 * WSZ, wtl + 3 * WSZ, outb);

    // 5) row-normalize + logits
    finalize_kernel<<<B, 128>>>(outb, W_pred, b_pred, logits);
}